// round 2
// baseline (speedup 1.0000x reference)
#include <cuda_runtime.h>
#include <cuda_bf16.h>
#include <math.h>

#define N 8192
#define FIN 256
#define FOUT 64
#define RPB 16   // rows per block in main kernel

// Scratch (module globals -- no allocation allowed in kernel_launch)
__device__ float  g_Wh[(size_t)N * FOUT];
__device__ float  g_WhP[(size_t)N * FOUT];  // pair-packed layout for main kernel
__device__ float4 g_fde[N];                 // {f_dst, exp(f_dst), exp(0.2 f_dst), f_src}
__device__ float  g_fdst[N];
__device__ float  g_gmax;

// packed f32x2 FMA: d = a*b + d (elementwise on the two packed fp32 lanes)
#define FMA_F32X2(d, a, b) \
    asm("fma.rn.f32x2 %0, %1, %2, %0;" : "+l"(d) : "l"(a), "l"(b))

// ---------------------------------------------------------------------------
// Kernel A: Wh = h @ W   (8192x256 @ 256x64)
// Also writes the pair-packed layout g_WhP:
//   float4 at [jp][lane] = {Wh[2jp][2l], Wh[2jp+1][2l], Wh[2jp][2l+1], Wh[2jp+1][2l+1]}
// ---------------------------------------------------------------------------
__global__ __launch_bounds__(256) void wh_kernel(const float* __restrict__ h,
                                                 const float* __restrict__ W) {
    __shared__ float Ws[128][FOUT];
    const int f = threadIdx.x & 63;
    const int g = threadIdx.x >> 6;            // 0..3
    const int row0 = blockIdx.x * 32 + g * 8;  // 32 rows per block

    float acc[8];
#pragma unroll
    for (int r = 0; r < 8; r++) acc[r] = 0.f;

    for (int t = 0; t < 2; t++) {
        __syncthreads();
        for (int idx = threadIdx.x; idx < 128 * FOUT; idx += 256)
            (&Ws[0][0])[idx] = W[t * 128 * FOUT + idx];
        __syncthreads();
#pragma unroll 1
        for (int r = 0; r < 8; r++) {
            const float4* hrow =
                (const float4*)(h + (size_t)(row0 + r) * FIN + t * 128);
            float a0 = acc[r];
#pragma unroll
            for (int k4 = 0; k4 < 32; k4++) {
                float4 hv = hrow[k4];
                a0 += hv.x * Ws[k4 * 4 + 0][f];
                a0 += hv.y * Ws[k4 * 4 + 1][f];
                a0 += hv.z * Ws[k4 * 4 + 2][f];
                a0 += hv.w * Ws[k4 * 4 + 3][f];
            }
            acc[r] = a0;
        }
    }
#pragma unroll
    for (int r = 0; r < 8; r++) {
        const int row = row0 + r;
        g_Wh[(size_t)row * FOUT + f] = acc[r];
        // packed-pair layout
        const int jp = row >> 1;
        const size_t pidx =
            (size_t)jp * 128 + (f >> 1) * 4 + (f & 1) * 2 + (row & 1);
        g_WhP[pidx] = acc[r];
    }
}

// ---------------------------------------------------------------------------
// Kernel B: per-node scalars + factorized exponentials
//   f_src[i] = Wh[i,:].a[0:64], f_dst[i] = Wh[i,:].a[64:128]
//   g_fde[i] = {f_dst, exp(f_dst), exp(0.2 f_dst), f_src}
// ---------------------------------------------------------------------------
__global__ void fvec_kernel(const float* __restrict__ a) {
    const int i = blockIdx.x * blockDim.x + threadIdx.x;
    const float4* w4 = (const float4*)(g_Wh + (size_t)i * FOUT);
    const float4* a4 = (const float4*)a;
    float s = 0.f, d = 0.f;
#pragma unroll
    for (int q = 0; q < 16; q++) {
        float4 v = w4[q];
        float4 as_ = a4[q];
        float4 ad = a4[16 + q];
        s += v.x * as_.x + v.y * as_.y + v.z * as_.z + v.w * as_.w;
        d += v.x * ad.x + v.y * ad.y + v.z * ad.z + v.w * ad.w;
    }
    g_fdst[i] = d;
    g_fde[i] = make_float4(d, __expf(d), __expf(0.2f * d), s);
}

// ---------------------------------------------------------------------------
// Kernel C: gmax = max_j f_dst[j]
// ---------------------------------------------------------------------------
__global__ void gmax_kernel() {
    __shared__ float red[1024];
    float m = -1e30f;
    for (int i = threadIdx.x; i < N; i += 1024) m = fmaxf(m, g_fdst[i]);
    red[threadIdx.x] = m;
    __syncthreads();
    for (int s = 512; s > 0; s >>= 1) {
        if (threadIdx.x < s)
            red[threadIdx.x] = fmaxf(red[threadIdx.x], red[threadIdx.x + s]);
        __syncthreads();
    }
    if (threadIdx.x == 0) g_gmax = red[0];
}

// ---------------------------------------------------------------------------
// Kernel D: fused masked softmax + (attention @ Wh) + ELU, NO per-edge exp.
//   p_ij = adj ? ((s>0) ? A1_i*E1_j : A2_i*E2_j) : 0,  s = fs_i + fd_j
// with A1_i = exp(fs_i - M_i), A2_i = exp(0.2 fs_i - M_i),
//      E1_j = exp(fd_j), E2_j = exp(0.2 fd_j), M_i = lrelu(fs_i + gmax).
// Block = 16 rows, 8 warps over disjoint j-chunks of 32.
// Phase A: lane = j, compute p for 16 rows -> smem.
// Phase B: lane = f-pair, packed-pair FFMA2 accumulation (2 j's x 2 f's / inst).
// ---------------------------------------------------------------------------
__global__ __launch_bounds__(256) void gat_main_kernel(const int* __restrict__ adj,
                                                       float* __restrict__ out) {
    __shared__ float  sp[8][RPB][32];      // 16 KB  p values [warp][row][jj]
    __shared__ float4 srow[RPB];           // {fs, A1, A2, -}
    __shared__ float  sacc4[4][RPB][64];   // 16 KB  staged cross-warp reduce
    __shared__ float  sl4[4][RPB];

    const int row0 = blockIdx.x * RPB;
    const int lane = threadIdx.x & 31;
    const int warp = threadIdx.x >> 5;

    if (threadIdx.x < RPB) {
        const float fs = g_fde[row0 + threadIdx.x].w;
        float M = fs + g_gmax;
        M = M > 0.f ? M : 0.2f * M;  // lrelu is monotone -> valid row upper bound
        srow[threadIdx.x] =
            make_float4(fs, __expf(fs - M), __expf(0.2f * fs - M), 0.f);
    }
    __syncthreads();

    unsigned long long acc0[RPB], acc1[RPB];  // packed {even-j part, odd-j part}
    float l[RPB];
#pragma unroll
    for (int r = 0; r < RPB; r++) { acc0[r] = 0ull; acc1[r] = 0ull; l[r] = 0.f; }

    const int* adj_base = adj + (size_t)row0 * N;

    for (int c = 0; c < 32; c++) {
        const int jb = (c * 8 + warp) * 32;
        const int j = jb + lane;

        __syncwarp();
        // ---- Phase A: p for this 32-j chunk, all 16 rows ----
        const float4 fde = g_fde[j];  // {fd, E1, E2, fs}
#pragma unroll
        for (int r = 0; r < RPB; r++) {
            const int av = adj_base[(size_t)r * N + j];
            const float4 rw = srow[r];
            const float s = rw.x + fde.x;
            float v = (s > 0.f ? rw.y : rw.z) * (s > 0.f ? fde.y : fde.z);
            v = av ? v : 0.f;
            l[r] += v;
            sp[warp][r][lane] = v;
        }
        __syncwarp();

        // ---- Phase B: packed accumulation over 16 j-pairs ----
        const ulonglong2* wp =
            ((const ulonglong2*)g_WhP) + ((size_t)(jb >> 1)) * 32 + lane;
#pragma unroll 4
        for (int q = 0; q < 16; q++) {
            const ulonglong2 wv = wp[(size_t)q * 32];
#pragma unroll
            for (int r = 0; r < RPB; r++) {
                const unsigned long long p2 =
                    *(const unsigned long long*)&sp[warp][r][2 * q];
                FMA_F32X2(acc0[r], p2, wv.x);
                FMA_F32X2(acc1[r], p2, wv.y);
            }
        }
    }

    // reduce l across lanes of the warp
#pragma unroll
    for (int r = 0; r < RPB; r++) {
#pragma unroll
        for (int off = 16; off > 0; off >>= 1)
            l[r] += __shfl_xor_sync(0xffffffffu, l[r], off);
    }

    // collapse packed halves -> per-f scalars
    float a0[RPB], a1[RPB];
#pragma unroll
    for (int r = 0; r < RPB; r++) {
        a0[r] = __uint_as_float((unsigned)acc0[r]) +
                __uint_as_float((unsigned)(acc0[r] >> 32));
        a1[r] = __uint_as_float((unsigned)acc1[r]) +
                __uint_as_float((unsigned)(acc1[r] >> 32));
    }

    // staged cross-warp reduction: warps 4..7 write, warps 0..3 add their own
    if (warp >= 4) {
#pragma unroll
        for (int r = 0; r < RPB; r++) {
            sacc4[warp - 4][r][2 * lane] = a0[r];
            sacc4[warp - 4][r][2 * lane + 1] = a1[r];
        }
        if (lane == 0) {
#pragma unroll
            for (int r = 0; r < RPB; r++) sl4[warp - 4][r] = l[r];
        }
    }
    __syncthreads();
    if (warp < 4) {
#pragma unroll
        for (int r = 0; r < RPB; r++) {
            sacc4[warp][r][2 * lane] += a0[r];
            sacc4[warp][r][2 * lane + 1] += a1[r];
        }
        if (lane == 0) {
#pragma unroll
            for (int r = 0; r < RPB; r++) sl4[warp][r] += l[r];
        }
    }
    __syncthreads();

    for (int idx = threadIdx.x; idx < RPB * 64; idx += 256) {
        const int r = idx >> 6, f = idx & 63;
        float s = 0.f, lt = 0.f;
#pragma unroll
        for (int w = 0; w < 4; w++) {
            s += sacc4[w][r][f];
            lt += sl4[w][r];
        }
        float o = s / lt;
        o = o > 0.f ? o : expm1f(o);  // ELU (alpha=1)
        out[(size_t)(row0 + r) * FOUT + f] = o;
    }
}

// ---------------------------------------------------------------------------
extern "C" void kernel_launch(void* const* d_in, const int* in_sizes, int n_in,
                              void* d_out, int out_size) {
    const float* h = (const float*)d_in[0];
    const int* adj = (const int*)d_in[1];
    const float* W = (const float*)d_in[2];
    const float* a = (const float*)d_in[3];
    float* out = (float*)d_out;

    wh_kernel<<<N / 32, 256>>>(h, W);
    fvec_kernel<<<N / 256, 256>>>(a);
    gmax_kernel<<<1, 1024>>>();
    gat_main_kernel<<<N / RPB, 256>>>(adj, out);
}

// round 3
// speedup vs baseline: 1.2636x; 1.2636x over previous
#include <cuda_runtime.h>
#include <cuda_bf16.h>
#include <math.h>

#define N 8192
#define FIN 256
#define FOUT 64
#define RPB 16   // rows per block in main kernel

// Scratch (module globals -- no allocation allowed in kernel_launch)
__device__ float  g_Wh[(size_t)N * FOUT];
__device__ float  g_WhP[(size_t)N * FOUT];  // pair-packed layout for main kernel
__device__ float2 g_epack[N];               // {exp(f_dst), exp(0.2 f_dst)}
__device__ float  g_fsrc[N];
__device__ float  g_fdst[N];
__device__ float  g_gmax;

// packed f32x2 ops
#define FMA_F32X2(d, a, b) \
    asm("fma.rn.f32x2 %0, %1, %2, %0;" : "+l"(d) : "l"(a), "l"(b))
#define MUL_F32X2(d, a, b) \
    asm("mul.rn.f32x2 %0, %1, %2;" : "=l"(d) : "l"(a), "l"(b))

// ---------------------------------------------------------------------------
// Kernel A: Wh = h @ W   (8192x256 @ 256x64)  + pair-packed copy g_WhP
//   float4 at [jp][lane] = {Wh[2jp][2l], Wh[2jp+1][2l], Wh[2jp][2l+1], Wh[2jp+1][2l+1]}
// ---------------------------------------------------------------------------
__global__ __launch_bounds__(256) void wh_kernel(const float* __restrict__ h,
                                                 const float* __restrict__ W) {
    __shared__ float Ws[128][FOUT];
    const int f = threadIdx.x & 63;
    const int g = threadIdx.x >> 6;            // 0..3
    const int row0 = blockIdx.x * 32 + g * 8;  // 32 rows per block

    float acc[8];
#pragma unroll
    for (int r = 0; r < 8; r++) acc[r] = 0.f;

    for (int t = 0; t < 2; t++) {
        __syncthreads();
        for (int idx = threadIdx.x; idx < 128 * FOUT; idx += 256)
            (&Ws[0][0])[idx] = W[t * 128 * FOUT + idx];
        __syncthreads();
#pragma unroll 1
        for (int r = 0; r < 8; r++) {
            const float4* hrow =
                (const float4*)(h + (size_t)(row0 + r) * FIN + t * 128);
            float a0 = acc[r];
#pragma unroll
            for (int k4 = 0; k4 < 32; k4++) {
                float4 hv = hrow[k4];
                a0 += hv.x * Ws[k4 * 4 + 0][f];
                a0 += hv.y * Ws[k4 * 4 + 1][f];
                a0 += hv.z * Ws[k4 * 4 + 2][f];
                a0 += hv.w * Ws[k4 * 4 + 3][f];
            }
            acc[r] = a0;
        }
    }
#pragma unroll
    for (int r = 0; r < 8; r++) {
        const int row = row0 + r;
        g_Wh[(size_t)row * FOUT + f] = acc[r];
        const int jp = row >> 1;
        const size_t pidx =
            (size_t)jp * 128 + (f >> 1) * 4 + (f & 1) * 2 + (row & 1);
        g_WhP[pidx] = acc[r];
    }
}

// ---------------------------------------------------------------------------
// Kernel B: per-node scalars + factorized exponentials
// ---------------------------------------------------------------------------
__global__ void fvec_kernel(const float* __restrict__ a) {
    const int i = blockIdx.x * blockDim.x + threadIdx.x;
    const float4* w4 = (const float4*)(g_Wh + (size_t)i * FOUT);
    const float4* a4 = (const float4*)a;
    float s = 0.f, d = 0.f;
#pragma unroll
    for (int q = 0; q < 16; q++) {
        float4 v = w4[q];
        float4 as_ = a4[q];
        float4 ad = a4[16 + q];
        s += v.x * as_.x + v.y * as_.y + v.z * as_.z + v.w * as_.w;
        d += v.x * ad.x + v.y * ad.y + v.z * ad.z + v.w * ad.w;
    }
    g_fsrc[i] = s;
    g_fdst[i] = d;
    g_epack[i] = make_float2(__expf(d), __expf(0.2f * d));
}

// ---------------------------------------------------------------------------
// Kernel C: gmax = max_j f_dst[j]
// ---------------------------------------------------------------------------
__global__ void gmax_kernel() {
    __shared__ float red[1024];
    float m = -1e30f;
    for (int i = threadIdx.x; i < N; i += 1024) m = fmaxf(m, g_fdst[i]);
    red[threadIdx.x] = m;
    __syncthreads();
    for (int s = 512; s > 0; s >>= 1) {
        if (threadIdx.x < s)
            red[threadIdx.x] = fmaxf(red[threadIdx.x], red[threadIdx.x + s]);
        __syncthreads();
    }
    if (threadIdx.x == 0) g_gmax = red[0];
}

// ---------------------------------------------------------------------------
// Kernel D: fused masked softmax + (attention @ Wh) + ELU.
//   p_ij = adj ? max(A1_i*E1_j, A2_i*E2_j) : 0          (exp is monotone)
// A1_i = exp(fs_i - M_i), A2_i = exp(0.2 fs_i - M_i), M_i = lrelu(fs_i + gmax)
// E1_j = exp(fd_j), E2_j = exp(0.2 fd_j).
// Block = 16 rows, 8 warps over disjoint j-chunks of 32, 2 CTAs/SM.
// Phase A: lane = j, p for 16 rows -> smem (adj prefetched a chunk ahead).
// Phase B: packed-pair FFMA2 (2 j x 2 f per inst), LDS.128 for p.
// ---------------------------------------------------------------------------
__global__ __launch_bounds__(256, 2) void gat_main_kernel(
    const int* __restrict__ adj, float* __restrict__ out) {
    __shared__ float  sp[8][RPB][32];            // 16 KB  p [warp][row][jj]
    __shared__ unsigned long long srowp[RPB];    // packed {A1, A2} per row
    __shared__ float  sacc4[4][RPB][64];         // 16 KB staged reduce
    __shared__ float  sl4[4][RPB];

    const int row0 = blockIdx.x * RPB;
    const int lane = threadIdx.x & 31;
    const int warp = threadIdx.x >> 5;

    if (threadIdx.x < RPB) {
        const float fs = g_fsrc[row0 + threadIdx.x];
        float M = fs + g_gmax;
        M = M > 0.f ? M : 0.2f * M;  // lrelu monotone -> valid row upper bound
        float2 A = make_float2(__expf(fs - M), __expf(0.2f * fs - M));
        srowp[threadIdx.x] = *(unsigned long long*)&A;
    }
    __syncthreads();

    unsigned long long acc0[RPB], acc1[RPB];  // packed over j-parity
    float l[RPB];
#pragma unroll
    for (int r = 0; r < RPB; r++) { acc0[r] = 0ull; acc1[r] = 0ull; l[r] = 0.f; }

    const int* adj_base = adj + (size_t)row0 * N;

    // prefetch adj for chunk 0 of this warp
    int av[RPB];
    {
        const int j0 = warp * 32 + lane;
#pragma unroll
        for (int r = 0; r < RPB; r++) av[r] = adj_base[(size_t)r * N + j0];
    }

    for (int c = 0; c < 32; c++) {
        const int jb = (c * 8 + warp) * 32;
        const int j = jb + lane;

        // ---- Phase A: p for this 32-j chunk, all 16 rows ----
        const float2 ep2 = g_epack[j];
        const unsigned long long ep = *(const unsigned long long*)&ep2;
#pragma unroll
        for (int r = 0; r < RPB; r++) {
            unsigned long long t;
            MUL_F32X2(t, srowp[r], ep);  // {A1*E1, A2*E2}
            float v = fmaxf(__uint_as_float((unsigned)t),
                            __uint_as_float((unsigned)(t >> 32)));
            v = av[r] ? v : 0.f;
            l[r] += v;
            sp[warp][r][lane] = v;
        }
        // prefetch adj for next chunk (latency hidden under Phase B)
        if (c < 31) {
            const int jn = jb + 256 + lane;
#pragma unroll
            for (int r = 0; r < RPB; r++) av[r] = adj_base[(size_t)r * N + jn];
        }
        __syncwarp();

        // ---- Phase B: packed accumulation, LDS.128 for p quads ----
        const ulonglong2* wp =
            ((const ulonglong2*)g_WhP) + ((size_t)(jb >> 1)) * 32 + lane;
#pragma unroll 2
        for (int q2 = 0; q2 < 8; q2++) {
            const ulonglong2 wa = wp[(size_t)(2 * q2) * 32];
            const ulonglong2 wb = wp[(size_t)(2 * q2 + 1) * 32];
#pragma unroll
            for (int r = 0; r < RPB; r++) {
                const ulonglong2 pp =
                    *(const ulonglong2*)&sp[warp][r][4 * q2];
                FMA_F32X2(acc0[r], pp.x, wa.x);
                FMA_F32X2(acc1[r], pp.x, wa.y);
                FMA_F32X2(acc0[r], pp.y, wb.x);
                FMA_F32X2(acc1[r], pp.y, wb.y);
            }
        }
        __syncwarp();
    }

    // reduce l across lanes of the warp
#pragma unroll
    for (int r = 0; r < RPB; r++) {
#pragma unroll
        for (int off = 16; off > 0; off >>= 1)
            l[r] += __shfl_xor_sync(0xffffffffu, l[r], off);
    }

    // collapse packed halves -> per-f scalars
    float a0[RPB], a1[RPB];
#pragma unroll
    for (int r = 0; r < RPB; r++) {
        a0[r] = __uint_as_float((unsigned)acc0[r]) +
                __uint_as_float((unsigned)(acc0[r] >> 32));
        a1[r] = __uint_as_float((unsigned)acc1[r]) +
                __uint_as_float((unsigned)(acc1[r] >> 32));
    }

    // staged cross-warp reduction: warps 4..7 write, warps 0..3 add their own
    if (warp >= 4) {
#pragma unroll
        for (int r = 0; r < RPB; r++) {
            sacc4[warp - 4][r][2 * lane] = a0[r];
            sacc4[warp - 4][r][2 * lane + 1] = a1[r];
        }
        if (lane == 0) {
#pragma unroll
            for (int r = 0; r < RPB; r++) sl4[warp - 4][r] = l[r];
        }
    }
    __syncthreads();
    if (warp < 4) {
#pragma unroll
        for (int r = 0; r < RPB; r++) {
            sacc4[warp][r][2 * lane] += a0[r];
            sacc4[warp][r][2 * lane + 1] += a1[r];
        }
        if (lane == 0) {
#pragma unroll
            for (int r = 0; r < RPB; r++) sl4[warp][r] += l[r];
        }
    }
    __syncthreads();

    for (int idx = threadIdx.x; idx < RPB * 64; idx += 256) {
        const int r = idx >> 6, f = idx & 63;
        float s = 0.f, lt = 0.f;
#pragma unroll
        for (int w = 0; w < 4; w++) {
            s += sacc4[w][r][f];
            lt += sl4[w][r];
        }
        float o = s / lt;
        o = o > 0.f ? o : expm1f(o);  // ELU (alpha=1)
        out[(size_t)(row0 + r) * FOUT + f] = o;
    }
}

// ---------------------------------------------------------------------------
extern "C" void kernel_launch(void* const* d_in, const int* in_sizes, int n_in,
                              void* d_out, int out_size) {
    const float* h = (const float*)d_in[0];
    const int* adj = (const int*)d_in[1];
    const float* W = (const float*)d_in[2];
    const float* a = (const float*)d_in[3];
    float* out = (float*)d_out;

    wh_kernel<<<N / 32, 256>>>(h, W);
    fvec_kernel<<<N / 256, 256>>>(a);
    gmax_kernel<<<1, 1024>>>();
    gat_main_kernel<<<N / RPB, 256>>>(adj, out);
}

// round 4
// speedup vs baseline: 1.3232x; 1.0472x over previous
#include <cuda_runtime.h>
#include <cuda_bf16.h>
#include <math.h>

#define N 8192
#define FIN 256
#define FOUT 64
#define RPB 16   // rows per block in main kernel

// Scratch (module globals -- no allocation allowed in kernel_launch)
__device__ float    g_Wh[(size_t)N * FOUT];
__device__ float    g_WhP[(size_t)N * FOUT];  // pair-packed layout
__device__ float2   g_epack[N];               // {exp(f_dst), exp(0.2 f_dst)}
__device__ float    g_fsrc[N];
__device__ unsigned g_gmax_enc;               // order-preserving encoded fp32 max

// packed f32x2 ops
#define FMA_F32X2(d, a, b) \
    asm("fma.rn.f32x2 %0, %1, %2, %0;" : "+l"(d) : "l"(a), "l"(b))
#define MUL_F32X2(d, a, b) \
    asm("mul.rn.f32x2 %0, %1, %2;" : "=l"(d) : "l"(a), "l"(b))

#define CP_ASYNC16(saddr, gptr) \
    asm volatile("cp.async.cg.shared.global [%0], [%1], 16;" ::"r"(saddr), "l"(gptr))
#define CP_COMMIT() asm volatile("cp.async.commit_group;")
#define CP_WAIT(n)  asm volatile("cp.async.wait_group %0;" ::"n"(n))

__device__ __forceinline__ unsigned enc_f(float x) {
    unsigned b = __float_as_uint(x);
    return (b & 0x80000000u) ? ~b : (b | 0x80000000u);
}
__device__ __forceinline__ float dec_f(unsigned k) {
    return __uint_as_float((k & 0x80000000u) ? (k & 0x7fffffffu) : ~k);
}

// ---------------------------------------------------------------------------
// Kernel A: Wh = h @ W  (+ pair-packed copy g_WhP). 16 rows/block, grid=512.
// Block 0 thread 0 also resets the gmax atomic for this launch.
// ---------------------------------------------------------------------------
__global__ __launch_bounds__(256) void wh_kernel(const float* __restrict__ h,
                                                 const float* __restrict__ W) {
    __shared__ float Ws[128][FOUT];
    if (blockIdx.x == 0 && threadIdx.x == 0) g_gmax_enc = 0u;

    const int f = threadIdx.x & 63;
    const int g = threadIdx.x >> 6;            // 0..3
    const int row0 = blockIdx.x * 16 + g * 4;  // 16 rows per block

    float acc[4];
#pragma unroll
    for (int r = 0; r < 4; r++) acc[r] = 0.f;

    for (int t = 0; t < 2; t++) {
        __syncthreads();
        for (int idx = threadIdx.x; idx < 128 * FOUT; idx += 256)
            (&Ws[0][0])[idx] = W[t * 128 * FOUT + idx];
        __syncthreads();
#pragma unroll
        for (int r = 0; r < 4; r++) {
            const float4* hrow =
                (const float4*)(h + (size_t)(row0 + r) * FIN + t * 128);
            float a0 = acc[r];
#pragma unroll
            for (int k4 = 0; k4 < 32; k4++) {
                float4 hv = hrow[k4];
                a0 += hv.x * Ws[k4 * 4 + 0][f];
                a0 += hv.y * Ws[k4 * 4 + 1][f];
                a0 += hv.z * Ws[k4 * 4 + 2][f];
                a0 += hv.w * Ws[k4 * 4 + 3][f];
            }
            acc[r] = a0;
        }
    }
#pragma unroll
    for (int r = 0; r < 4; r++) {
        const int row = row0 + r;
        g_Wh[(size_t)row * FOUT + f] = acc[r];
        const int jp = row >> 1;
        const size_t pidx =
            (size_t)jp * 128 + (f >> 1) * 4 + (f & 1) * 2 + (row & 1);
        g_WhP[pidx] = acc[r];
    }
}

// ---------------------------------------------------------------------------
// Kernel B: per-node scalars, factorized exps, fused global max of f_dst.
// ---------------------------------------------------------------------------
__global__ __launch_bounds__(256) void fvec_kernel(const float* __restrict__ a) {
    __shared__ unsigned smax[8];
    const int i = blockIdx.x * blockDim.x + threadIdx.x;
    const float4* w4 = (const float4*)(g_Wh + (size_t)i * FOUT);
    const float4* a4 = (const float4*)a;
    float s = 0.f, d = 0.f;
#pragma unroll
    for (int q = 0; q < 16; q++) {
        float4 v = w4[q];
        float4 as_ = a4[q];
        float4 ad = a4[16 + q];
        s += v.x * as_.x + v.y * as_.y + v.z * as_.z + v.w * as_.w;
        d += v.x * ad.x + v.y * ad.y + v.z * ad.z + v.w * ad.w;
    }
    g_fsrc[i] = s;
    g_epack[i] = make_float2(__expf(d), __expf(0.2f * d));

    // block max of d -> one atomic per block
    unsigned k = enc_f(d);
#pragma unroll
    for (int off = 16; off > 0; off >>= 1)
        k = max(k, __shfl_xor_sync(0xffffffffu, k, off));
    if ((threadIdx.x & 31) == 0) smax[threadIdx.x >> 5] = k;
    __syncthreads();
    if (threadIdx.x == 0) {
        unsigned m = smax[0];
#pragma unroll
        for (int w = 1; w < 8; w++) m = max(m, smax[w]);
        atomicMax(&g_gmax_enc, m);
    }
}

// ---------------------------------------------------------------------------
// Kernel D: fused masked softmax + (attention @ Wh) + ELU.
//   p_ij = adj ? max(A1_i*E1_j, A2_i*E2_j) : 0          (exp is monotone)
// Block = 16 rows, 8 warps over disjoint j-chunks of 32, 2 CTAs/SM.
// adj staged via cp.async double buffer; Wh pair-packed, register-double-
// buffered LDG.128; FFMA2 accumulation (2 j x 2 f per instruction).
// ---------------------------------------------------------------------------
__global__ __launch_bounds__(256, 2) void gat_main_kernel(
    const int* __restrict__ adj, float* __restrict__ out) {
    __shared__ float  sp[8][RPB][32];          // 16 KB  p [warp][row][jj]
    __shared__ int    sadj[8][2][RPB][32];     // 32 KB  adj double buffer
    __shared__ unsigned long long srowp[RPB];  // packed {A1, A2} per row
    __shared__ float  sacc4[4][RPB][64];       // 16 KB staged reduce
    __shared__ float  sl4[4][RPB];

    const int row0 = blockIdx.x * RPB;
    const int lane = threadIdx.x & 31;
    const int warp = threadIdx.x >> 5;

    if (threadIdx.x < RPB) {
        const float fs = g_fsrc[row0 + threadIdx.x];
        const float gmax = dec_f(g_gmax_enc);
        float M = fs + gmax;
        M = M > 0.f ? M : 0.2f * M;  // lrelu monotone -> valid row upper bound
        float2 A = make_float2(__expf(fs - M), __expf(0.2f * fs - M));
        srowp[threadIdx.x] = *(unsigned long long*)&A;
    }
    __syncthreads();

    unsigned long long acc0[RPB], acc1[RPB];  // packed over j-parity
    float l[RPB];
#pragma unroll
    for (int r = 0; r < RPB; r++) { acc0[r] = 0ull; acc1[r] = 0ull; l[r] = 0.f; }

    const int* adj_base = adj + (size_t)row0 * N;

    // cp.async issue helper geometry: lane covers rows {r4, r4+4, r4+8, r4+12},
    // 4 consecutive j starting at jq.
    const int r4 = lane >> 3;
    const int jq = (lane & 7) * 4;

    // prologue: stage chunk 0 into buffer 0
    {
        const int jb = warp * 32;
#pragma unroll
        for (int rr = 0; rr < 4; rr++) {
            const int r = rr * 4 + r4;
            const unsigned saddr =
                (unsigned)__cvta_generic_to_shared(&sadj[warp][0][r][jq]);
            CP_ASYNC16(saddr, adj_base + (size_t)r * N + jb + jq);
        }
        CP_COMMIT();
    }

    for (int c = 0; c < 32; c++) {
        const int jb = (c * 8 + warp) * 32;
        const int buf = c & 1;

        // stage next chunk into the other buffer
        if (c < 31) {
            const int jbn = jb + 256;
#pragma unroll
            for (int rr = 0; rr < 4; rr++) {
                const int r = rr * 4 + r4;
                const unsigned saddr = (unsigned)__cvta_generic_to_shared(
                    &sadj[warp][buf ^ 1][r][jq]);
                CP_ASYNC16(saddr, adj_base + (size_t)r * N + jbn + jq);
            }
            CP_COMMIT();
            CP_WAIT(1);  // chunk c's group complete
        } else {
            CP_WAIT(0);
        }
        __syncwarp();

        // ---- Phase A: p for this 32-j chunk, all 16 rows ----
        const float2 ep2 = g_epack[jb + lane];
        const unsigned long long ep = *(const unsigned long long*)&ep2;
#pragma unroll
        for (int r = 0; r < RPB; r++) {
            unsigned long long t;
            MUL_F32X2(t, srowp[r], ep);  // {A1*E1, A2*E2}
            float v = fmaxf(__uint_as_float((unsigned)t),
                            __uint_as_float((unsigned)(t >> 32)));
            v = sadj[warp][buf][r][lane] ? v : 0.f;
            l[r] += v;
            sp[warp][r][lane] = v;
        }
        __syncwarp();

        // ---- Phase B: packed FFMA2, register-double-buffered Wh loads ----
        const ulonglong2* wp =
            ((const ulonglong2*)g_WhP) + ((size_t)(jb >> 1)) * 32 + lane;
        ulonglong2 wa = wp[0];
        ulonglong2 wb = wp[32];
#pragma unroll
        for (int q2 = 0; q2 < 8; q2++) {
            ulonglong2 wa_n, wb_n;
            if (q2 < 7) {
                wa_n = wp[(size_t)(2 * q2 + 2) * 32];
                wb_n = wp[(size_t)(2 * q2 + 3) * 32];
            }
#pragma unroll
            for (int r = 0; r < RPB; r++) {
                const ulonglong2 pp = *(const ulonglong2*)&sp[warp][r][4 * q2];
                FMA_F32X2(acc0[r], pp.x, wa.x);
                FMA_F32X2(acc1[r], pp.x, wa.y);
                FMA_F32X2(acc0[r], pp.y, wb.x);
                FMA_F32X2(acc1[r], pp.y, wb.y);
            }
            if (q2 < 7) { wa = wa_n; wb = wb_n; }
        }
        __syncwarp();
    }

    // reduce l across lanes of the warp
#pragma unroll
    for (int r = 0; r < RPB; r++) {
#pragma unroll
        for (int off = 16; off > 0; off >>= 1)
            l[r] += __shfl_xor_sync(0xffffffffu, l[r], off);
    }

    // collapse packed halves -> per-f scalars
    float a0[RPB], a1[RPB];
#pragma unroll
    for (int r = 0; r < RPB; r++) {
        a0[r] = __uint_as_float((unsigned)acc0[r]) +
                __uint_as_float((unsigned)(acc0[r] >> 32));
        a1[r] = __uint_as_float((unsigned)acc1[r]) +
                __uint_as_float((unsigned)(acc1[r] >> 32));
    }

    // staged cross-warp reduction: warps 4..7 write, warps 0..3 add their own
    if (warp >= 4) {
#pragma unroll
        for (int r = 0; r < RPB; r++) {
            sacc4[warp - 4][r][2 * lane] = a0[r];
            sacc4[warp - 4][r][2 * lane + 1] = a1[r];
        }
        if (lane == 0) {
#pragma unroll
            for (int r = 0; r < RPB; r++) sl4[warp - 4][r] = l[r];
        }
    }
    __syncthreads();
    if (warp < 4) {
#pragma unroll
        for (int r = 0; r < RPB; r++) {
            sacc4[warp][r][2 * lane] += a0[r];
            sacc4[warp][r][2 * lane + 1] += a1[r];
        }
        if (lane == 0) {
#pragma unroll
            for (int r = 0; r < RPB; r++) sl4[warp][r] += l[r];
        }
    }
    __syncthreads();

    for (int idx = threadIdx.x; idx < RPB * 64; idx += 256) {
        const int r = idx >> 6, f = idx & 63;
        float s = 0.f, lt = 0.f;
#pragma unroll
        for (int w = 0; w < 4; w++) {
            s += sacc4[w][r][f];
            lt += sl4[w][r];
        }
        float o = s / lt;
        o = o > 0.f ? o : expm1f(o);  // ELU (alpha=1)
        out[(size_t)(row0 + r) * FOUT + f] = o;
    }
}

// ---------------------------------------------------------------------------
extern "C" void kernel_launch(void* const* d_in, const int* in_sizes, int n_in,
                              void* d_out, int out_size) {
    const float* h = (const float*)d_in[0];
    const int* adj = (const int*)d_in[1];
    const float* W = (const float*)d_in[2];
    const float* a = (const float*)d_in[3];
    float* out = (float*)d_out;

    wh_kernel<<<N / 16, 256>>>(h, W);
    fvec_kernel<<<N / 256, 256>>>(a);
    gat_main_kernel<<<N / RPB, 256>>>(adj, out);
}